// round 8
// baseline (speedup 1.0000x reference)
#include <cuda_runtime.h>
#include <cuda_bf16.h>
#include <cstdint>

#define NN 40000
#define NP 40064          // padded: 313 * 128
#define EE 640000
#define HH 128
#define GG 16
#define CC 10

// Scratch (static device globals). 16B aligned for float4.
__device__ __align__(16) float g_h[NP * HH];     // activations
__device__ __align__(16) float g_g[NP * HH];     // g = (h@W) * dis
__device__ __align__(16) float g_dis[NP];        // deg_inv_sqrt
__device__ int   g_deg[NN];
__device__ int   g_rowptr[NN + 1];
__device__ int   g_cursor[NN];
__device__ int   g_col[EE];
__device__ __align__(16) float g_pool[GG * HH + GG];

// ===========================================================================
// CSR build
// ===========================================================================
__global__ void deg_kernel(const int* __restrict__ dst) {
    int e0 = 4 * (blockIdx.x * blockDim.x + threadIdx.x);
#pragma unroll
    for (int j = 0; j < 4; j++) {
        int e = e0 + j;
        if (e < EE) atomicAdd(&g_deg[dst[e]], 1);
    }
}

// Exclusive scan of g_deg -> g_rowptr/g_cursor, plus dis = rsqrt(deg+1).
__global__ void scan_kernel() {
    __shared__ int s[1024];
    const int CH = 40;
    int t = threadIdx.x;
    int base = t * CH;
    int sum = 0;
    for (int i = 0; i < CH; i++) {
        int n = base + i;
        if (n < NN) sum += g_deg[n];
    }
    s[t] = sum;
    __syncthreads();
    for (int off = 1; off < 1024; off <<= 1) {
        int v = (t >= off) ? s[t - off] : 0;
        __syncthreads();
        s[t] += v;
        __syncthreads();
    }
    int run = (t == 0) ? 0 : s[t - 1];
    for (int i = 0; i < CH; i++) {
        int n = base + i;
        if (n < NN) {
            int d = g_deg[n];
            g_rowptr[n] = run;
            g_cursor[n] = run;
            g_dis[n] = rsqrtf((float)d + 1.0f);
            run += d;
        }
    }
    if (t == 1023) g_rowptr[NN] = EE;
}

__global__ void fill_kernel(const int* __restrict__ src,
                            const int* __restrict__ dst) {
    int e0 = 4 * (blockIdx.x * blockDim.x + threadIdx.x);
#pragma unroll
    for (int j = 0; j < 4; j++) {
        int e = e0 + j;
        if (e < EE) {
            int pos = atomicAdd(&g_cursor[dst[e]], 1);
            g_col[pos] = src[e];
        }
    }
}

// ===========================================================================
// HMMA GEMM: out[NP,128] = A[.,128] @ W[128,128]  (bf16x3 via mma.sync, f32 acc)
// Block: 128 rows x 128 cols, 256 threads (8 warps), warp tile 32x64.
// EPI 0: out += bias[col];  EPI 1: out *= dis[row].
// ===========================================================================
#define ASTR 272                         // smem row stride in bytes (136 bf16)
#define SM_AH 0
#define SM_AL (SM_AH + 128 * ASTR)       // 34816
#define SM_BH (SM_AL + 128 * ASTR)       // 69632
#define SM_BL (SM_BH + 128 * ASTR)       // 104448
#define SM_GEMM_TOTAL (SM_BL + 128 * ASTR)  // 139264

__device__ __forceinline__ void mma_bf16(float* c, const uint32_t* a, const uint32_t* b) {
    asm volatile(
        "mma.sync.aligned.m16n8k16.row.col.f32.bf16.bf16.f32 "
        "{%0,%1,%2,%3}, {%4,%5,%6,%7}, {%8,%9}, {%0,%1,%2,%3};\n"
        : "+f"(c[0]), "+f"(c[1]), "+f"(c[2]), "+f"(c[3])
        : "r"(a[0]), "r"(a[1]), "r"(a[2]), "r"(a[3]), "r"(b[0]), "r"(b[1]));
}

// split two floats into packed bf16x2 hi and lo (lo = residual)
__device__ __forceinline__ void split2(float a, float b, uint32_t& hi, uint32_t& lo) {
    __nv_bfloat16 ah = __float2bfloat16(a);
    __nv_bfloat16 bh = __float2bfloat16(b);
    __nv_bfloat16 al = __float2bfloat16(a - __bfloat162float(ah));
    __nv_bfloat16 bl = __float2bfloat16(b - __bfloat162float(bh));
    hi = (uint32_t)__bfloat16_as_ushort(ah) | ((uint32_t)__bfloat16_as_ushort(bh) << 16);
    lo = (uint32_t)__bfloat16_as_ushort(al) | ((uint32_t)__bfloat16_as_ushort(bl) << 16);
}

template <int EPI>
__global__ __launch_bounds__(256, 1)
void gemm_mma(const float* __restrict__ A,
              const float* __restrict__ W,
              const float* __restrict__ bias_or_dis,
              float* __restrict__ out, int mclamp) {
    extern __shared__ char sm[];
    const int tid = threadIdx.x;       // 256
    const int row0 = blockIdx.x * 128;

    // --- Convert A tile (128x128 f32) -> Ah/Al bf16 [row][k], stride ASTR ---
    const float4* A4base = (const float4*)A;
#pragma unroll
    for (int i = 0; i < 16; i++) {
        int idx = i * 256 + tid;       // 0..4095
        int row = idx >> 5;
        int q = idx & 31;
        int gr = row0 + row;
        if (gr > mclamp) gr = mclamp;
        float4 v = A4base[(size_t)gr * 32 + q];
        uint32_t h0, l0, h1, l1;
        split2(v.x, v.y, h0, l0);
        split2(v.z, v.w, h1, l1);
        char* pa = sm + row * ASTR + q * 8;
        *(uint32_t*)(pa + SM_AH) = h0;
        *(uint32_t*)(pa + SM_AH + 4) = h1;
        *(uint32_t*)(pa + SM_AL) = l0;
        *(uint32_t*)(pa + SM_AL + 4) = l1;
    }

    // --- Convert W (128x128 f32, [k][n]) -> Bh/Bl transposed [n][k] ---
    const float4* W4 = (const float4*)W;
#pragma unroll
    for (int i = 0; i < 16; i++) {
        int idx = i * 256 + tid;
        int k = idx >> 5;
        int q = idx & 31;
        int n0 = q * 4;
        float4 v = W4[(size_t)k * 32 + q];
        const float vv[4] = {v.x, v.y, v.z, v.w};
#pragma unroll
        for (int j = 0; j < 4; j++) {
            __nv_bfloat16 hi = __float2bfloat16(vv[j]);
            __nv_bfloat16 lo = __float2bfloat16(vv[j] - __bfloat162float(hi));
            char* pb = sm + (n0 + j) * ASTR + k * 2;
            *(__nv_bfloat16*)(pb + SM_BH) = hi;
            *(__nv_bfloat16*)(pb + SM_BL) = lo;
        }
    }
    __syncthreads();

    // --- MMA mainloop: warp w -> rows (w&3)*32, cols (w>>2)*64 ---
    const int w = tid >> 5;
    const int lane = tid & 31;
    const int gq = lane >> 2;      // group id 0..7
    const int tq = lane & 3;       // thread-in-group 0..3
    const int r0 = (w & 3) * 32;
    const int c0 = (w >> 2) * 64;

    float acc[2][8][4];
#pragma unroll
    for (int mi = 0; mi < 2; mi++)
#pragma unroll
        for (int ni = 0; ni < 8; ni++)
#pragma unroll
            for (int j = 0; j < 4; j++) acc[mi][ni][j] = 0.0f;

#pragma unroll
    for (int kb = 0; kb < 8; kb++) {
        const int k0 = kb * 16;
        uint32_t ah[2][4], al[2][4];
#pragma unroll
        for (int mi = 0; mi < 2; mi++) {
            int rr = r0 + mi * 16 + gq;
            const char* p0 = sm + rr * ASTR + (k0 + tq * 2) * 2;
            const char* p1 = sm + (rr + 8) * ASTR + (k0 + tq * 2) * 2;
            ah[mi][0] = *(const uint32_t*)(p0 + SM_AH);
            ah[mi][1] = *(const uint32_t*)(p1 + SM_AH);
            ah[mi][2] = *(const uint32_t*)(p0 + SM_AH + 16);
            ah[mi][3] = *(const uint32_t*)(p1 + SM_AH + 16);
            al[mi][0] = *(const uint32_t*)(p0 + SM_AL);
            al[mi][1] = *(const uint32_t*)(p1 + SM_AL);
            al[mi][2] = *(const uint32_t*)(p0 + SM_AL + 16);
            al[mi][3] = *(const uint32_t*)(p1 + SM_AL + 16);
        }
        uint32_t bh[8][2], bl[8][2];
#pragma unroll
        for (int ni = 0; ni < 8; ni++) {
            int nn = c0 + ni * 8 + gq;
            const char* pb = sm + nn * ASTR + (k0 + tq * 2) * 2;
            bh[ni][0] = *(const uint32_t*)(pb + SM_BH);
            bh[ni][1] = *(const uint32_t*)(pb + SM_BH + 16);
            bl[ni][0] = *(const uint32_t*)(pb + SM_BL);
            bl[ni][1] = *(const uint32_t*)(pb + SM_BL + 16);
        }
#pragma unroll
        for (int ni = 0; ni < 8; ni++) {
            mma_bf16(acc[0][ni], ah[0], bh[ni]);
            mma_bf16(acc[1][ni], ah[1], bh[ni]);
            mma_bf16(acc[0][ni], ah[0], bl[ni]);
            mma_bf16(acc[1][ni], ah[1], bl[ni]);
            mma_bf16(acc[0][ni], al[0], bh[ni]);
            mma_bf16(acc[1][ni], al[1], bh[ni]);
        }
    }

    // --- Epilogue: direct global stores (float2) ---
#pragma unroll
    for (int mi = 0; mi < 2; mi++) {
        int r = row0 + r0 + mi * 16 + gq;
        float s0 = 0.f, s1 = 0.f;
        if (EPI == 1) { s0 = bias_or_dis[r]; s1 = bias_or_dis[r + 8]; }
#pragma unroll
        for (int ni = 0; ni < 8; ni++) {
            int c = c0 + ni * 8 + tq * 2;
            float2 v0, v1;
            if (EPI == 0) {
                float b0 = bias_or_dis[c], b1 = bias_or_dis[c + 1];
                v0 = make_float2(acc[mi][ni][0] + b0, acc[mi][ni][1] + b1);
                v1 = make_float2(acc[mi][ni][2] + b0, acc[mi][ni][3] + b1);
            } else {
                v0 = make_float2(acc[mi][ni][0] * s0, acc[mi][ni][1] * s0);
                v1 = make_float2(acc[mi][ni][2] * s1, acc[mi][ni][3] * s1);
            }
            *(float2*)(out + (size_t)r * 128 + c) = v0;
            *(float2*)(out + (size_t)(r + 8) * 128 + c) = v1;
        }
    }
}

// ===========================================================================
// CSR gather + fused finalize: one warp per node.
// h[n] = relu(dis[n] * (sum_{e in in(n)} g[col[e]] + g[n]) + b)
// ===========================================================================
__global__ void gather_kernel(const float* __restrict__ b) {
    int w = (blockIdx.x * blockDim.x + threadIdx.x) >> 5;
    if (w >= NN) return;
    int lane = threadIdx.x & 31;
    int beg = g_rowptr[w];
    int end = g_rowptr[w + 1];

    const float4* G = (const float4*)g_g;
    float4 a0 = G[(size_t)w * 32 + lane];   // self term
    float4 a1 = make_float4(0.f, 0.f, 0.f, 0.f);

    int e = beg;
    while (e < end) {
        int cnt = min(end - e, 32);
        int c = (lane < cnt) ? g_col[e + lane] : 0;
        int i = 0;
        for (; i + 4 <= cnt; i += 4) {
            int s0 = __shfl_sync(0xffffffffu, c, i);
            int s1 = __shfl_sync(0xffffffffu, c, i + 1);
            int s2 = __shfl_sync(0xffffffffu, c, i + 2);
            int s3 = __shfl_sync(0xffffffffu, c, i + 3);
            float4 v0 = G[(size_t)s0 * 32 + lane];
            float4 v1 = G[(size_t)s1 * 32 + lane];
            float4 v2 = G[(size_t)s2 * 32 + lane];
            float4 v3 = G[(size_t)s3 * 32 + lane];
            a0.x += v0.x; a0.y += v0.y; a0.z += v0.z; a0.w += v0.w;
            a1.x += v1.x; a1.y += v1.y; a1.z += v1.z; a1.w += v1.w;
            a0.x += v2.x; a0.y += v2.y; a0.z += v2.z; a0.w += v2.w;
            a1.x += v3.x; a1.y += v3.y; a1.z += v3.z; a1.w += v3.w;
        }
        for (; i < cnt; i++) {
            int s0 = __shfl_sync(0xffffffffu, c, i);
            float4 v0 = G[(size_t)s0 * 32 + lane];
            a0.x += v0.x; a0.y += v0.y; a0.z += v0.z; a0.w += v0.w;
        }
        e += cnt;
    }
    a0.x += a1.x; a0.y += a1.y; a0.z += a1.z; a0.w += a1.w;

    float sc = g_dis[w];
    float4 bb = *(const float4*)(b + lane * 4);
    float4 o;
    o.x = fmaxf(fmaf(sc, a0.x, bb.x), 0.0f);
    o.y = fmaxf(fmaf(sc, a0.y, bb.y), 0.0f);
    o.z = fmaxf(fmaf(sc, a0.z, bb.z), 0.0f);
    o.w = fmaxf(fmaf(sc, a0.w, bb.w), 0.0f);
    *(float4*)(g_h + (size_t)w * 128 + lane * 4) = o;
}

// ===========================================================================
// Pool + head
// ===========================================================================
__global__ void pool_kernel(const int* __restrict__ batch) {
    __shared__ float s[GG * HH];
    __shared__ float c[GG];
    int tid = threadIdx.x;  // 128
#pragma unroll
    for (int i = 0; i < GG; i++) s[i * HH + tid] = 0.0f;
    if (tid < GG) c[tid] = 0.0f;
    __syncthreads();

    for (int n = blockIdx.x; n < NN; n += gridDim.x) {
        int b = batch[n];
        s[b * HH + tid] += g_h[(size_t)n * HH + tid];
        if (tid == 0) c[b] += 1.0f;
    }
    __syncthreads();
#pragma unroll
    for (int i = 0; i < GG; i++) atomicAdd(&g_pool[i * HH + tid], s[i * HH + tid]);
    if (tid < GG) atomicAdd(&g_pool[GG * HH + tid], c[tid]);
}

__global__ void head_kernel(const float* __restrict__ Wf1,
                            const float* __restrict__ bf1,
                            const float* __restrict__ Wf2,
                            const float* __restrict__ bf2,
                            float* __restrict__ out) {
    __shared__ float P[GG * HH];
    __shared__ float Z[GG * 64];
    int tid = threadIdx.x;

    for (int i = tid; i < GG * HH; i += 1024) {
        float cnt = g_pool[GG * HH + i / HH];
        P[i] = g_pool[i] / fmaxf(cnt, 1.0f);
    }
    __syncthreads();

    {
        int g = tid >> 6;
        int j = tid & 63;
        float acc = bf1[j];
        const float* p = P + g * HH;
#pragma unroll 8
        for (int k = 0; k < HH; k++) acc += p[k] * Wf1[k * 64 + j];
        Z[g * 64 + j] = fmaxf(acc, 0.0f);
    }
    __syncthreads();

    if (tid < GG * CC) {
        int g = tid / CC;
        int c = tid % CC;
        float acc = bf2[c];
        const float* z = Z + g * 64;
#pragma unroll
        for (int j = 0; j < 64; j++) acc += z[j] * Wf2[j * CC + c];
        out[g * CC + c] = acc;
    }
}

// ===========================================================================
extern "C" void kernel_launch(void* const* d_in, const int* in_sizes, int n_in,
                              void* d_out, int out_size) {
    const float* x = (const float*)d_in[0];
    const int* edge = (const int*)d_in[1];     // int32
    const int* batch = (const int*)d_in[2];    // int32
    const float* W_in = (const float*)d_in[3];
    const float* b_in = (const float*)d_in[4];
    const float* W1 = (const float*)d_in[5];
    const float* b1 = (const float*)d_in[6];
    const float* W2 = (const float*)d_in[7];
    const float* b2 = (const float*)d_in[8];
    const float* Wf1 = (const float*)d_in[9];
    const float* bf1 = (const float*)d_in[10];
    const float* Wf2 = (const float*)d_in[11];
    const float* bf2 = (const float*)d_in[12];
    float* out = (float*)d_out;

    const int* src = edge;
    const int* dst = edge + EE;

    void *p_deg, *p_pool, *p_h, *p_g, *p_dis;
    cudaGetSymbolAddress(&p_deg, g_deg);
    cudaGetSymbolAddress(&p_pool, g_pool);
    cudaGetSymbolAddress(&p_h, g_h);
    cudaGetSymbolAddress(&p_g, g_g);
    cudaGetSymbolAddress(&p_dis, g_dis);
    float* f_h = (float*)p_h;
    float* f_g = (float*)p_g;

    cudaFuncSetAttribute(gemm_mma<0>, cudaFuncAttributeMaxDynamicSharedMemorySize, SM_GEMM_TOTAL);
    cudaFuncSetAttribute(gemm_mma<1>, cudaFuncAttributeMaxDynamicSharedMemorySize, SM_GEMM_TOTAL);

    // CSR build + dis
    cudaMemsetAsync(p_deg, 0, NN * sizeof(int));
    deg_kernel<<<(EE / 4 + 255) / 256, 256>>>(dst);
    scan_kernel<<<1, 1024>>>();
    fill_kernel<<<(EE / 4 + 255) / 256, 256>>>(src, dst);

    const int gemmGrid = NP / 128;  // 313

    // h0 = x @ W_in + b_in
    gemm_mma<0><<<gemmGrid, 256, SM_GEMM_TOTAL>>>(x, W_in, b_in, f_h, NN - 1);

    // Layer 1: g = (h @ W1) * dis;  h = relu(dis*(gather + self) + b1)
    gemm_mma<1><<<gemmGrid, 256, SM_GEMM_TOTAL>>>(f_h, W1, (const float*)p_dis, f_g, NP - 1);
    gather_kernel<<<(NN * 32 + 255) / 256, 256>>>(b1);

    // Layer 2
    gemm_mma<1><<<gemmGrid, 256, SM_GEMM_TOTAL>>>(f_h, W2, (const float*)p_dis, f_g, NP - 1);
    gather_kernel<<<(NN * 32 + 255) / 256, 256>>>(b2);

    // Pool + head
    cudaMemsetAsync(p_pool, 0, (GG * HH + GG) * sizeof(float));
    pool_kernel<<<256, 128>>>(batch);
    head_kernel<<<1, 1024>>>(Wf1, bf1, Wf2, bf2, out);
}

// round 9
// speedup vs baseline: 1.4899x; 1.4899x over previous
#include <cuda_runtime.h>
#include <cuda_bf16.h>
#include <cstdint>

#define NN 40000
#define NP 40064          // padded: 313 * 128
#define EE 640000
#define HH 128
#define GG 16
#define CC 10

// Scratch (static device globals). 16B aligned.
__device__ __align__(16) __nv_bfloat16 g_pah[NP * HH];  // plane-pair A (hi/lo)
__device__ __align__(16) __nv_bfloat16 g_pal[NP * HH];
__device__ __align__(16) __nv_bfloat16 g_pbh[NP * HH];  // plane-pair B
__device__ __align__(16) __nv_bfloat16 g_pbl[NP * HH];
__device__ __align__(16) float g_g[NP * HH];            // g = (h@W)*dis, f32
__device__ __align__(16) float g_dis[NP];               // deg_inv_sqrt (pad rows stay 0)
__device__ __align__(16) __nv_bfloat16 g_wh[3 * HH * HH];  // W hi, transposed [n][k]
__device__ __align__(16) __nv_bfloat16 g_wl[3 * HH * HH];  // W lo
__device__ int   g_deg[NN];
__device__ int   g_rowptr[NN + 1];
__device__ int   g_cursor[NN];
__device__ int   g_col[EE];
__device__ int   g_bsum[64];
__device__ int   g_boff[64];
__device__ __align__(16) float g_pool[GG * HH + GG];

// split two floats into packed bf16x2 hi and lo (lo = residual)
__device__ __forceinline__ void split2(float a, float b, uint32_t& hi, uint32_t& lo) {
    __nv_bfloat16 ah = __float2bfloat16(a);
    __nv_bfloat16 bh = __float2bfloat16(b);
    __nv_bfloat16 al = __float2bfloat16(a - __bfloat162float(ah));
    __nv_bfloat16 bl = __float2bfloat16(b - __bfloat162float(bh));
    hi = (uint32_t)__bfloat16_as_ushort(ah) | ((uint32_t)__bfloat16_as_ushort(bh) << 16);
    lo = (uint32_t)__bfloat16_as_ushort(al) | ((uint32_t)__bfloat16_as_ushort(bl) << 16);
}

// ===========================================================================
// CSR build (coalesced multi-block scan)
// ===========================================================================
__global__ void deg_kernel(const int* __restrict__ dst) {
    int e0 = 4 * (blockIdx.x * blockDim.x + threadIdx.x);
#pragma unroll
    for (int j = 0; j < 4; j++) {
        int e = e0 + j;
        if (e < EE) atomicAdd(&g_deg[dst[e]], 1);
    }
}

// Pass 1: per-block inclusive scan of deg; write local exclusive, block sums.
__global__ void scan1_kernel() {
    __shared__ int s[1024];
    int t = threadIdx.x;
    int n = blockIdx.x * 1024 + t;
    int d = (n < NN) ? g_deg[n] : 0;
    s[t] = d;
    __syncthreads();
    for (int off = 1; off < 1024; off <<= 1) {
        int v = (t >= off) ? s[t - off] : 0;
        __syncthreads();
        s[t] += v;
        __syncthreads();
    }
    if (n < NN) g_rowptr[n] = s[t] - d;   // local exclusive
    if (t == 1023) g_bsum[blockIdx.x] = s[t];
}

// Pass 2: exclusive scan of 40 block sums (single warp-ish block).
__global__ void scan2_kernel() {
    __shared__ int s[64];
    int t = threadIdx.x;  // 64
    int v = (t < 40) ? g_bsum[t] : 0;
    s[t] = v;
    __syncthreads();
    for (int off = 1; off < 64; off <<= 1) {
        int u = (t >= off) ? s[t - off] : 0;
        __syncthreads();
        s[t] += u;
        __syncthreads();
    }
    if (t < 40) g_boff[t] = s[t] - v;
}

// Pass 3: add block offset; emit cursor + dis. Also rowptr[NN]=EE.
__global__ void scan3_kernel() {
    int n = blockIdx.x * 1024 + threadIdx.x;
    if (n >= NN) {
        if (n == NN) g_rowptr[NN] = EE;
        return;
    }
    int r = g_rowptr[n] + g_boff[blockIdx.x];
    g_rowptr[n] = r;
    g_cursor[n] = r;
    g_dis[n] = rsqrtf((float)g_deg[n] + 1.0f);
}

__global__ void fill_kernel(const int* __restrict__ src,
                            const int* __restrict__ dst) {
    int e0 = 4 * (blockIdx.x * blockDim.x + threadIdx.x);
#pragma unroll
    for (int j = 0; j < 4; j++) {
        int e = e0 + j;
        if (e < EE) {
            int pos = atomicAdd(&g_cursor[dst[e]], 1);
            g_col[pos] = src[e];
        }
    }
}

// ===========================================================================
// Conversion kernels
// ===========================================================================
// x f32 -> plane A (hi/lo), zero-pad rows >= NN
__global__ void conv_x_kernel(const float* __restrict__ x) {
    int idx = blockIdx.x * blockDim.x + threadIdx.x;  // 0 .. NP*32-1
    if (idx >= NP * 32) return;
    int row = idx >> 5;
    int q = idx & 31;
    float4 v = (row < NN) ? ((const float4*)x)[(size_t)row * 32 + q]
                          : make_float4(0.f, 0.f, 0.f, 0.f);
    uint32_t h0, l0, h1, l1;
    split2(v.x, v.y, h0, l0);
    split2(v.z, v.w, h1, l1);
    ((uint2*)g_pah)[idx] = make_uint2(h0, h1);
    ((uint2*)g_pal)[idx] = make_uint2(l0, l1);
}

// W [k][n] f32 -> Wh/Wl transposed [n][k] bf16, 3 matrices
__global__ void conv_w_kernel(const float* __restrict__ W0,
                              const float* __restrict__ W1,
                              const float* __restrict__ W2) {
    const float* W = (blockIdx.y == 0) ? W0 : (blockIdx.y == 1) ? W1 : W2;
    __nv_bfloat16* Wh = g_wh + blockIdx.y * HH * HH;
    __nv_bfloat16* Wl = g_wl + blockIdx.y * HH * HH;
    int idx = blockIdx.x * 256 + threadIdx.x;  // 0..16383
    int k = idx >> 7;
    int n = idx & 127;
    float v = W[k * 128 + n];
    __nv_bfloat16 hi = __float2bfloat16(v);
    __nv_bfloat16 lo = __float2bfloat16(v - __bfloat162float(hi));
    Wh[n * 128 + k] = hi;
    Wl[n * 128 + k] = lo;
}

// ===========================================================================
// HMMA GEMM on pre-split bf16 planes. Block 128x128, 256 thr, warp 32x64.
// EPI 0: +bias[col], write bf16 planes.  EPI 1: *dis[row], write f32 g.
// ===========================================================================
#define ASTR 272                         // smem row stride bytes (conflict-free frags)
#define SM_AH 0
#define SM_AL (SM_AH + 128 * ASTR)
#define SM_BH (SM_AL + 128 * ASTR)
#define SM_BL (SM_BH + 128 * ASTR)
#define SM_GEMM_TOTAL (SM_BL + 128 * ASTR)  // 139264

__device__ __forceinline__ void mma_bf16(float* c, const uint32_t* a, const uint32_t* b) {
    asm volatile(
        "mma.sync.aligned.m16n8k16.row.col.f32.bf16.bf16.f32 "
        "{%0,%1,%2,%3}, {%4,%5,%6,%7}, {%8,%9}, {%0,%1,%2,%3};\n"
        : "+f"(c[0]), "+f"(c[1]), "+f"(c[2]), "+f"(c[3])
        : "r"(a[0]), "r"(a[1]), "r"(a[2]), "r"(a[3]), "r"(b[0]), "r"(b[1]));
}

template <int EPI>
__global__ __launch_bounds__(256, 1)
void gemm2(const __nv_bfloat16* __restrict__ Ah,
           const __nv_bfloat16* __restrict__ Al,
           const __nv_bfloat16* __restrict__ Wh,
           const __nv_bfloat16* __restrict__ Wl,
           const float* __restrict__ bias_or_dis,
           float* __restrict__ outg,
           __nv_bfloat16* __restrict__ outh,
           __nv_bfloat16* __restrict__ outl) {
    extern __shared__ char sm[];
    const int tid = threadIdx.x;       // 256
    const int row0 = blockIdx.x * 128;

    // Copy 4 bf16 tiles (each 128 rows x 256B) into ASTR-strided smem.
    {
        const uint4* srcs[4] = {
            (const uint4*)(Ah + (size_t)row0 * 128),
            (const uint4*)(Al + (size_t)row0 * 128),
            (const uint4*)Wh,
            (const uint4*)Wl};
        const int offs[4] = {SM_AH, SM_AL, SM_BH, SM_BL};
#pragma unroll
        for (int p = 0; p < 4; p++) {
            const uint4* s4 = srcs[p];
            char* dbase = sm + offs[p];
#pragma unroll
            for (int i = 0; i < 8; i++) {
                int idx = i * 256 + tid;   // 0..2047
                int row = idx >> 4;
                int q = idx & 15;
                *(uint4*)(dbase + row * ASTR + q * 16) = s4[idx];
            }
        }
    }
    __syncthreads();

    const int w = tid >> 5;
    const int lane = tid & 31;
    const int gq = lane >> 2;
    const int tq = lane & 3;
    const int r0 = (w & 3) * 32;
    const int c0 = (w >> 2) * 64;

    float acc[2][8][4];
#pragma unroll
    for (int mi = 0; mi < 2; mi++)
#pragma unroll
        for (int ni = 0; ni < 8; ni++)
#pragma unroll
            for (int j = 0; j < 4; j++) acc[mi][ni][j] = 0.0f;

#pragma unroll
    for (int kb = 0; kb < 8; kb++) {
        const int k0 = kb * 16;
        uint32_t ah[2][4], al[2][4];
#pragma unroll
        for (int mi = 0; mi < 2; mi++) {
            int rr = r0 + mi * 16 + gq;
            const char* p0 = sm + rr * ASTR + (k0 + tq * 2) * 2;
            const char* p1 = sm + (rr + 8) * ASTR + (k0 + tq * 2) * 2;
            ah[mi][0] = *(const uint32_t*)(p0 + SM_AH);
            ah[mi][1] = *(const uint32_t*)(p1 + SM_AH);
            ah[mi][2] = *(const uint32_t*)(p0 + SM_AH + 16);
            ah[mi][3] = *(const uint32_t*)(p1 + SM_AH + 16);
            al[mi][0] = *(const uint32_t*)(p0 + SM_AL);
            al[mi][1] = *(const uint32_t*)(p1 + SM_AL);
            al[mi][2] = *(const uint32_t*)(p0 + SM_AL + 16);
            al[mi][3] = *(const uint32_t*)(p1 + SM_AL + 16);
        }
        uint32_t bh[8][2], bl[8][2];
#pragma unroll
        for (int ni = 0; ni < 8; ni++) {
            int nn = c0 + ni * 8 + gq;
            const char* pb = sm + nn * ASTR + (k0 + tq * 2) * 2;
            bh[ni][0] = *(const uint32_t*)(pb + SM_BH);
            bh[ni][1] = *(const uint32_t*)(pb + SM_BH + 16);
            bl[ni][0] = *(const uint32_t*)(pb + SM_BL);
            bl[ni][1] = *(const uint32_t*)(pb + SM_BL + 16);
        }
#pragma unroll
        for (int ni = 0; ni < 8; ni++) {
            mma_bf16(acc[0][ni], ah[0], bh[ni]);
            mma_bf16(acc[1][ni], ah[1], bh[ni]);
            mma_bf16(acc[0][ni], ah[0], bl[ni]);
            mma_bf16(acc[1][ni], ah[1], bl[ni]);
            mma_bf16(acc[0][ni], al[0], bh[ni]);
            mma_bf16(acc[1][ni], al[1], bh[ni]);
        }
    }

    // Epilogue
#pragma unroll
    for (int mi = 0; mi < 2; mi++) {
        int r = row0 + r0 + mi * 16 + gq;
        float s0 = 0.f, s1 = 0.f;
        if (EPI == 1) { s0 = bias_or_dis[r]; s1 = bias_or_dis[r + 8]; }
#pragma unroll
        for (int ni = 0; ni < 8; ni++) {
            int c = c0 + ni * 8 + tq * 2;
            if (EPI == 1) {
                *(float2*)(outg + (size_t)r * 128 + c) =
                    make_float2(acc[mi][ni][0] * s0, acc[mi][ni][1] * s0);
                *(float2*)(outg + (size_t)(r + 8) * 128 + c) =
                    make_float2(acc[mi][ni][2] * s1, acc[mi][ni][3] * s1);
            } else {
                float b0 = bias_or_dis[c], b1 = bias_or_dis[c + 1];
                uint32_t hi, lo;
                split2(acc[mi][ni][0] + b0, acc[mi][ni][1] + b1, hi, lo);
                ((uint32_t*)outh)[((size_t)r * 128 + c) >> 1] = hi;
                ((uint32_t*)outl)[((size_t)r * 128 + c) >> 1] = lo;
                split2(acc[mi][ni][2] + b0, acc[mi][ni][3] + b1, hi, lo);
                ((uint32_t*)outh)[((size_t)(r + 8) * 128 + c) >> 1] = hi;
                ((uint32_t*)outl)[((size_t)(r + 8) * 128 + c) >> 1] = lo;
            }
        }
    }
}

// ===========================================================================
// CSR gather + fused finalize: one warp per node, writes bf16 planes.
// h[n] = relu(dis[n] * (sum g[col[e]] + g[n]) + b)
// ===========================================================================
__global__ void gather_kernel(const float* __restrict__ b,
                              __nv_bfloat16* __restrict__ outh,
                              __nv_bfloat16* __restrict__ outl) {
    int w = (blockIdx.x * blockDim.x + threadIdx.x) >> 5;
    if (w >= NN) return;
    int lane = threadIdx.x & 31;
    int beg = g_rowptr[w];
    int end = g_rowptr[w + 1];

    const float4* G = (const float4*)g_g;
    float4 a0 = G[(size_t)w * 32 + lane];   // self term
    float4 a1 = make_float4(0.f, 0.f, 0.f, 0.f);

    int e = beg;
    while (e < end) {
        int cnt = min(end - e, 32);
        int c = (lane < cnt) ? g_col[e + lane] : 0;
        int i = 0;
        for (; i + 8 <= cnt; i += 8) {
            int s0 = __shfl_sync(0xffffffffu, c, i);
            int s1 = __shfl_sync(0xffffffffu, c, i + 1);
            int s2 = __shfl_sync(0xffffffffu, c, i + 2);
            int s3 = __shfl_sync(0xffffffffu, c, i + 3);
            int s4 = __shfl_sync(0xffffffffu, c, i + 4);
            int s5 = __shfl_sync(0xffffffffu, c, i + 5);
            int s6 = __shfl_sync(0xffffffffu, c, i + 6);
            int s7 = __shfl_sync(0xffffffffu, c, i + 7);
            float4 v0 = G[(size_t)s0 * 32 + lane];
            float4 v1 = G[(size_t)s1 * 32 + lane];
            float4 v2 = G[(size_t)s2 * 32 + lane];
            float4 v3 = G[(size_t)s3 * 32 + lane];
            float4 v4 = G[(size_t)s4 * 32 + lane];
            float4 v5 = G[(size_t)s5 * 32 + lane];
            float4 v6 = G[(size_t)s6 * 32 + lane];
            float4 v7 = G[(size_t)s7 * 32 + lane];
            a0.x += v0.x; a0.y += v0.y; a0.z += v0.z; a0.w += v0.w;
            a1.x += v1.x; a1.y += v1.y; a1.z += v1.z; a1.w += v1.w;
            a0.x += v2.x; a0.y += v2.y; a0.z += v2.z; a0.w += v2.w;
            a1.x += v3.x; a1.y += v3.y; a1.z += v3.z; a1.w += v3.w;
            a0.x += v4.x; a0.y += v4.y; a0.z += v4.z; a0.w += v4.w;
            a1.x += v5.x; a1.y += v5.y; a1.z += v5.z; a1.w += v5.w;
            a0.x += v6.x; a0.y += v6.y; a0.z += v6.z; a0.w += v6.w;
            a1.x += v7.x; a1.y += v7.y; a1.z += v7.z; a1.w += v7.w;
        }
        for (; i + 4 <= cnt; i += 4) {
            int s0 = __shfl_sync(0xffffffffu, c, i);
            int s1 = __shfl_sync(0xffffffffu, c, i + 1);
            int s2 = __shfl_sync(0xffffffffu, c, i + 2);
            int s3 = __shfl_sync(0xffffffffu, c, i + 3);
            float4 v0 = G[(size_t)s0 * 32 + lane];
            float4 v1 = G[(size_t)s1 * 32 + lane];
            float4 v2 = G[(size_t)s2 * 32 + lane];
            float4 v3 = G[(size_t)s3 * 32 + lane];
            a0.x += v0.x; a0.y += v0.y; a0.z += v0.z; a0.w += v0.w;
            a1.x += v1.x; a1.y += v1.y; a1.z += v1.z; a1.w += v1.w;
            a0.x += v2.x; a0.y += v2.y; a0.z += v2.z; a0.w += v2.w;
            a1.x += v3.x; a1.y += v3.y; a1.z += v3.z; a1.w += v3.w;
        }
        for (; i < cnt; i++) {
            int s0 = __shfl_sync(0xffffffffu, c, i);
            float4 v0 = G[(size_t)s0 * 32 + lane];
            a0.x += v0.x; a0.y += v0.y; a0.z += v0.z; a0.w += v0.w;
        }
        e += cnt;
    }
    a0.x += a1.x; a0.y += a1.y; a0.z += a1.z; a0.w += a1.w;

    float sc = g_dis[w];
    float4 bb = *(const float4*)(b + lane * 4);
    float4 o;
    o.x = fmaxf(fmaf(sc, a0.x, bb.x), 0.0f);
    o.y = fmaxf(fmaf(sc, a0.y, bb.y), 0.0f);
    o.z = fmaxf(fmaf(sc, a0.z, bb.z), 0.0f);
    o.w = fmaxf(fmaf(sc, a0.w, bb.w), 0.0f);

    uint32_t h0, l0, h1, l1;
    split2(o.x, o.y, h0, l0);
    split2(o.z, o.w, h1, l1);
    ((uint2*)outh)[(size_t)w * 32 + lane] = make_uint2(h0, h1);
    ((uint2*)outl)[(size_t)w * 32 + lane] = make_uint2(l0, l1);
}

// ===========================================================================
// Pool (reads bf16 planes) + head
// ===========================================================================
__global__ void pool_kernel(const int* __restrict__ batch,
                            const __nv_bfloat16* __restrict__ ph,
                            const __nv_bfloat16* __restrict__ pl) {
    __shared__ float s[GG * HH];
    __shared__ float c[GG];
    int tid = threadIdx.x;  // 128
#pragma unroll
    for (int i = 0; i < GG; i++) s[i * HH + tid] = 0.0f;
    if (tid < GG) c[tid] = 0.0f;
    __syncthreads();

    for (int n = blockIdx.x; n < NN; n += gridDim.x) {
        int b = batch[n];
        float v = __bfloat162float(ph[(size_t)n * HH + tid]) +
                  __bfloat162float(pl[(size_t)n * HH + tid]);
        s[b * HH + tid] += v;
        if (tid == 0) c[b] += 1.0f;
    }
    __syncthreads();
#pragma unroll
    for (int i = 0; i < GG; i++) atomicAdd(&g_pool[i * HH + tid], s[i * HH + tid]);
    if (tid < GG) atomicAdd(&g_pool[GG * HH + tid], c[tid]);
}

__global__ void head_kernel(const float* __restrict__ Wf1,
                            const float* __restrict__ bf1,
                            const float* __restrict__ Wf2,
                            const float* __restrict__ bf2,
                            float* __restrict__ out) {
    __shared__ float P[GG * HH];
    __shared__ float Z[GG * 64];
    int tid = threadIdx.x;

    for (int i = tid; i < GG * HH; i += 1024) {
        float cnt = g_pool[GG * HH + i / HH];
        P[i] = g_pool[i] / fmaxf(cnt, 1.0f);
    }
    __syncthreads();

    {
        int g = tid >> 6;
        int j = tid & 63;
        float acc = bf1[j];
        const float* p = P + g * HH;
#pragma unroll 8
        for (int k = 0; k < HH; k++) acc += p[k] * Wf1[k * 64 + j];
        Z[g * 64 + j] = fmaxf(acc, 0.0f);
    }
    __syncthreads();

    if (tid < GG * CC) {
        int g = tid / CC;
        int c = tid % CC;
        float acc = bf2[c];
        const float* z = Z + g * 64;
#pragma unroll
        for (int j = 0; j < 64; j++) acc += z[j] * Wf2[j * CC + c];
        out[g * CC + c] = acc;
    }
}

// ===========================================================================
extern "C" void kernel_launch(void* const* d_in, const int* in_sizes, int n_in,
                              void* d_out, int out_size) {
    const float* x = (const float*)d_in[0];
    const int* edge = (const int*)d_in[1];     // int32
    const int* batch = (const int*)d_in[2];    // int32
    const float* W_in = (const float*)d_in[3];
    const float* b_in = (const float*)d_in[4];
    const float* W1 = (const float*)d_in[5];
    const float* b1 = (const float*)d_in[6];
    const float* W2 = (const float*)d_in[7];
    const float* b2 = (const float*)d_in[8];
    const float* Wf1 = (const float*)d_in[9];
    const float* bf1 = (const float*)d_in[10];
    const float* Wf2 = (const float*)d_in[11];
    const float* bf2 = (const float*)d_in[12];
    float* out = (float*)d_out;

    const int* src = edge;
    const int* dst = edge + EE;

    void *p_deg, *p_pool, *p_g, *p_dis;
    void *p_pah, *p_pal, *p_pbh, *p_pbl, *p_wh, *p_wl;
    cudaGetSymbolAddress(&p_deg, g_deg);
    cudaGetSymbolAddress(&p_pool, g_pool);
    cudaGetSymbolAddress(&p_g, g_g);
    cudaGetSymbolAddress(&p_dis, g_dis);
    cudaGetSymbolAddress(&p_pah, g_pah);
    cudaGetSymbolAddress(&p_pal, g_pal);
    cudaGetSymbolAddress(&p_pbh, g_pbh);
    cudaGetSymbolAddress(&p_pbl, g_pbl);
    cudaGetSymbolAddress(&p_wh, g_wh);
    cudaGetSymbolAddress(&p_wl, g_wl);
    __nv_bfloat16* pah = (__nv_bfloat16*)p_pah;
    __nv_bfloat16* pal = (__nv_bfloat16*)p_pal;
    __nv_bfloat16* pbh = (__nv_bfloat16*)p_pbh;
    __nv_bfloat16* pbl = (__nv_bfloat16*)p_pbl;
    __nv_bfloat16* wh = (__nv_bfloat16*)p_wh;
    __nv_bfloat16* wl = (__nv_bfloat16*)p_wl;
    float* fg = (float*)p_g;

    cudaFuncSetAttribute(gemm2<0>, cudaFuncAttributeMaxDynamicSharedMemorySize, SM_GEMM_TOTAL);
    cudaFuncSetAttribute(gemm2<1>, cudaFuncAttributeMaxDynamicSharedMemorySize, SM_GEMM_TOTAL);

    // CSR build + dis (coalesced scan)
    cudaMemsetAsync(p_deg, 0, NN * sizeof(int));
    deg_kernel<<<(EE / 4 + 255) / 256, 256>>>(dst);
    scan1_kernel<<<40, 1024>>>();
    scan2_kernel<<<1, 64>>>();
    scan3_kernel<<<40, 1024>>>();
    fill_kernel<<<(EE / 4 + 255) / 256, 256>>>(src, dst);

    // Conversions
    conv_w_kernel<<<dim3(64, 3), 256>>>(W_in, W1, W2);
    conv_x_kernel<<<(NP * 32 + 255) / 256, 256>>>(x);

    const int gemmGrid = NP / 128;  // 313

    // h0 = x @ W_in + b_in  (planes A -> planes B)
    gemm2<0><<<gemmGrid, 256, SM_GEMM_TOTAL>>>(pah, pal, wh, wl, b_in,
                                               nullptr, pbh, pbl);
    // Layer 1: g = (h0 @ W1) * dis; h1 = relu(dis*(gather+self)+b1) -> planes A
    gemm2<1><<<gemmGrid, 256, SM_GEMM_TOTAL>>>(pbh, pbl, wh + HH * HH, wl + HH * HH,
                                               (const float*)p_dis, fg, nullptr, nullptr);
    gather_kernel<<<(NN * 32 + 255) / 256, 256>>>(b1, pah, pal);

    // Layer 2: planes A -> g -> planes B
    gemm2<1><<<gemmGrid, 256, SM_GEMM_TOTAL>>>(pah, pal, wh + 2 * HH * HH, wl + 2 * HH * HH,
                                               (const float*)p_dis, fg, nullptr, nullptr);
    gather_kernel<<<(NN * 32 + 255) / 256, 256>>>(b2, pbh, pbl);

    // Pool + head
    cudaMemsetAsync(p_pool, 0, (GG * HH + GG) * sizeof(float));
    pool_kernel<<<256, 128>>>(batch, pbh, pbl);
    head_kernel<<<1, 1024>>>(Wf1, bf1, Wf2, bf2, out);
}

// round 10
// speedup vs baseline: 1.5194x; 1.0198x over previous
#include <cuda_runtime.h>
#include <cuda_bf16.h>
#include <cstdint>

#define NN 40000
#define NP 40064          // padded: 313 * 128
#define EE 640000
#define HH 128
#define GG 16
#define CC 10

// Scratch (static device globals). 16B aligned.
__device__ __align__(16) __nv_bfloat16 g_pah[NP * HH];  // plane-pair A (hi/lo)
__device__ __align__(16) __nv_bfloat16 g_pal[NP * HH];
__device__ __align__(16) __nv_bfloat16 g_pbh[NP * HH];  // plane-pair B
__device__ __align__(16) __nv_bfloat16 g_pbl[NP * HH];
__device__ __align__(16) __nv_bfloat16 g_gb[NP * HH];   // g = (h@W)*dis, bf16
__device__ __align__(16) float g_dis[NP];               // deg_inv_sqrt
__device__ __align__(16) __nv_bfloat16 g_wh[3 * HH * HH];  // W hi, transposed [n][k]
__device__ __align__(16) __nv_bfloat16 g_wl[3 * HH * HH];  // W lo
__device__ int   g_deg[NN];
__device__ int   g_rowptr[NN + 1];
__device__ int   g_cursor[NN];
__device__ int   g_col[EE];
__device__ int   g_bsum[64];
__device__ int   g_boff[64];
__device__ __align__(16) float g_pool[GG * HH + GG];

// split two floats into packed bf16x2 hi and lo (lo = residual)
__device__ __forceinline__ void split2(float a, float b, uint32_t& hi, uint32_t& lo) {
    __nv_bfloat16 ah = __float2bfloat16(a);
    __nv_bfloat16 bh = __float2bfloat16(b);
    __nv_bfloat16 al = __float2bfloat16(a - __bfloat162float(ah));
    __nv_bfloat16 bl = __float2bfloat16(b - __bfloat162float(bh));
    hi = (uint32_t)__bfloat16_as_ushort(ah) | ((uint32_t)__bfloat16_as_ushort(bh) << 16);
    lo = (uint32_t)__bfloat16_as_ushort(al) | ((uint32_t)__bfloat16_as_ushort(bl) << 16);
}

__device__ __forceinline__ uint32_t pack_bf2(float a, float b) {
    __nv_bfloat162 t = __floats2bfloat162_rn(a, b);   // low = a, high = b
    return *(uint32_t*)&t;
}

__device__ __forceinline__ float2 unpack_bf2(uint32_t u) {
    return __bfloat1622float2(*(__nv_bfloat162*)&u);  // .x = low, .y = high
}

// ===========================================================================
// CSR build (coalesced multi-block scan)
// ===========================================================================
__global__ void deg_kernel(const int* __restrict__ dst) {
    int e0 = 4 * (blockIdx.x * blockDim.x + threadIdx.x);
#pragma unroll
    for (int j = 0; j < 4; j++) {
        int e = e0 + j;
        if (e < EE) atomicAdd(&g_deg[dst[e]], 1);
    }
}

__global__ void scan1_kernel() {
    __shared__ int s[1024];
    int t = threadIdx.x;
    int n = blockIdx.x * 1024 + t;
    int d = (n < NN) ? g_deg[n] : 0;
    s[t] = d;
    __syncthreads();
    for (int off = 1; off < 1024; off <<= 1) {
        int v = (t >= off) ? s[t - off] : 0;
        __syncthreads();
        s[t] += v;
        __syncthreads();
    }
    if (n < NN) g_rowptr[n] = s[t] - d;   // local exclusive
    if (t == 1023) g_bsum[blockIdx.x] = s[t];
}

__global__ void scan2_kernel() {
    __shared__ int s[64];
    int t = threadIdx.x;  // 64
    int v = (t < 40) ? g_bsum[t] : 0;
    s[t] = v;
    __syncthreads();
    for (int off = 1; off < 64; off <<= 1) {
        int u = (t >= off) ? s[t - off] : 0;
        __syncthreads();
        s[t] += u;
        __syncthreads();
    }
    if (t < 40) g_boff[t] = s[t] - v;
}

__global__ void scan3_kernel() {
    int n = blockIdx.x * 1024 + threadIdx.x;
    if (n >= NN) {
        if (n == NN) g_rowptr[NN] = EE;
        return;
    }
    int r = g_rowptr[n] + g_boff[blockIdx.x];
    g_rowptr[n] = r;
    g_cursor[n] = r;
    g_dis[n] = rsqrtf((float)g_deg[n] + 1.0f);
}

__global__ void fill_kernel(const int* __restrict__ src,
                            const int* __restrict__ dst) {
    int e0 = 4 * (blockIdx.x * blockDim.x + threadIdx.x);
#pragma unroll
    for (int j = 0; j < 4; j++) {
        int e = e0 + j;
        if (e < EE) {
            int pos = atomicAdd(&g_cursor[dst[e]], 1);
            g_col[pos] = src[e];
        }
    }
}

// ===========================================================================
// Conversion kernels
// ===========================================================================
__global__ void conv_x_kernel(const float* __restrict__ x) {
    int idx = blockIdx.x * blockDim.x + threadIdx.x;  // 0 .. NP*32-1
    if (idx >= NP * 32) return;
    int row = idx >> 5;
    int q = idx & 31;
    float4 v = (row < NN) ? ((const float4*)x)[(size_t)row * 32 + q]
                          : make_float4(0.f, 0.f, 0.f, 0.f);
    uint32_t h0, l0, h1, l1;
    split2(v.x, v.y, h0, l0);
    split2(v.z, v.w, h1, l1);
    ((uint2*)g_pah)[idx] = make_uint2(h0, h1);
    ((uint2*)g_pal)[idx] = make_uint2(l0, l1);
}

__global__ void conv_w_kernel(const float* __restrict__ W0,
                              const float* __restrict__ W1,
                              const float* __restrict__ W2) {
    const float* W = (blockIdx.y == 0) ? W0 : (blockIdx.y == 1) ? W1 : W2;
    __nv_bfloat16* Wh = g_wh + blockIdx.y * HH * HH;
    __nv_bfloat16* Wl = g_wl + blockIdx.y * HH * HH;
    int idx = blockIdx.x * 256 + threadIdx.x;  // 0..16383
    int k = idx >> 7;
    int n = idx & 127;
    float v = W[k * 128 + n];
    __nv_bfloat16 hi = __float2bfloat16(v);
    __nv_bfloat16 lo = __float2bfloat16(v - __bfloat162float(hi));
    Wh[n * 128 + k] = hi;
    Wl[n * 128 + k] = lo;
}

// ===========================================================================
// HMMA GEMM on pre-split bf16 planes. Block 128x128, 256 thr, warp 32x64.
// EPI 0: +bias[col], write bf16 hi/lo planes.  EPI 1: *dis[row], write bf16 g.
// ===========================================================================
#define ASTR 272
#define SM_AH 0
#define SM_AL (SM_AH + 128 * ASTR)
#define SM_BH (SM_AL + 128 * ASTR)
#define SM_BL (SM_BH + 128 * ASTR)
#define SM_GEMM_TOTAL (SM_BL + 128 * ASTR)  // 139264

__device__ __forceinline__ void mma_bf16(float* c, const uint32_t* a, const uint32_t* b) {
    asm volatile(
        "mma.sync.aligned.m16n8k16.row.col.f32.bf16.bf16.f32 "
        "{%0,%1,%2,%3}, {%4,%5,%6,%7}, {%8,%9}, {%0,%1,%2,%3};\n"
        : "+f"(c[0]), "+f"(c[1]), "+f"(c[2]), "+f"(c[3])
        : "r"(a[0]), "r"(a[1]), "r"(a[2]), "r"(a[3]), "r"(b[0]), "r"(b[1]));
}

template <int EPI>
__global__ __launch_bounds__(256, 1)
void gemm2(const __nv_bfloat16* __restrict__ Ah,
           const __nv_bfloat16* __restrict__ Al,
           const __nv_bfloat16* __restrict__ Wh,
           const __nv_bfloat16* __restrict__ Wl,
           const float* __restrict__ bias_or_dis,
           __nv_bfloat16* __restrict__ outgb,
           __nv_bfloat16* __restrict__ outh,
           __nv_bfloat16* __restrict__ outl) {
    extern __shared__ char sm[];
    const int tid = threadIdx.x;       // 256
    const int row0 = blockIdx.x * 128;

    // Copy 4 bf16 tiles (each 128 rows x 256B) into ASTR-strided smem.
    {
        const uint4* srcs[4] = {
            (const uint4*)(Ah + (size_t)row0 * 128),
            (const uint4*)(Al + (size_t)row0 * 128),
            (const uint4*)Wh,
            (const uint4*)Wl};
        const int offs[4] = {SM_AH, SM_AL, SM_BH, SM_BL};
#pragma unroll
        for (int p = 0; p < 4; p++) {
            const uint4* s4 = srcs[p];
            char* dbase = sm + offs[p];
#pragma unroll
            for (int i = 0; i < 8; i++) {
                int idx = i * 256 + tid;   // 0..2047
                int row = idx >> 4;
                int q = idx & 15;
                *(uint4*)(dbase + row * ASTR + q * 16) = s4[idx];
            }
        }
    }
    __syncthreads();

    const int w = tid >> 5;
    const int lane = tid & 31;
    const int gq = lane >> 2;
    const int tq = lane & 3;
    const int r0 = (w & 3) * 32;
    const int c0 = (w >> 2) * 64;

    float acc[2][8][4];
#pragma unroll
    for (int mi = 0; mi < 2; mi++)
#pragma unroll
        for (int ni = 0; ni < 8; ni++)
#pragma unroll
            for (int j = 0; j < 4; j++) acc[mi][ni][j] = 0.0f;

#pragma unroll
    for (int kb = 0; kb < 8; kb++) {
        const int k0 = kb * 16;
        uint32_t ah[2][4], al[2][4];
#pragma unroll
        for (int mi = 0; mi < 2; mi++) {
            int rr = r0 + mi * 16 + gq;
            const char* p0 = sm + rr * ASTR + (k0 + tq * 2) * 2;
            const char* p1 = sm + (rr + 8) * ASTR + (k0 + tq * 2) * 2;
            ah[mi][0] = *(const uint32_t*)(p0 + SM_AH);
            ah[mi][1] = *(const uint32_t*)(p1 + SM_AH);
            ah[mi][2] = *(const uint32_t*)(p0 + SM_AH + 16);
            ah[mi][3] = *(const uint32_t*)(p1 + SM_AH + 16);
            al[mi][0] = *(const uint32_t*)(p0 + SM_AL);
            al[mi][1] = *(const uint32_t*)(p1 + SM_AL);
            al[mi][2] = *(const uint32_t*)(p0 + SM_AL + 16);
            al[mi][3] = *(const uint32_t*)(p1 + SM_AL + 16);
        }
        uint32_t bh[8][2], bl[8][2];
#pragma unroll
        for (int ni = 0; ni < 8; ni++) {
            int nn = c0 + ni * 8 + gq;
            const char* pb = sm + nn * ASTR + (k0 + tq * 2) * 2;
            bh[ni][0] = *(const uint32_t*)(pb + SM_BH);
            bh[ni][1] = *(const uint32_t*)(pb + SM_BH + 16);
            bl[ni][0] = *(const uint32_t*)(pb + SM_BL);
            bl[ni][1] = *(const uint32_t*)(pb + SM_BL + 16);
        }
#pragma unroll
        for (int ni = 0; ni < 8; ni++) {
            mma_bf16(acc[0][ni], ah[0], bh[ni]);
            mma_bf16(acc[1][ni], ah[1], bh[ni]);
            mma_bf16(acc[0][ni], ah[0], bl[ni]);
            mma_bf16(acc[1][ni], ah[1], bl[ni]);
            mma_bf16(acc[0][ni], al[0], bh[ni]);
            mma_bf16(acc[1][ni], al[1], bh[ni]);
        }
    }

    // Epilogue
#pragma unroll
    for (int mi = 0; mi < 2; mi++) {
        int r = row0 + r0 + mi * 16 + gq;
        float s0 = 0.f, s1 = 0.f;
        if (EPI == 1) { s0 = bias_or_dis[r]; s1 = bias_or_dis[r + 8]; }
#pragma unroll
        for (int ni = 0; ni < 8; ni++) {
            int c = c0 + ni * 8 + tq * 2;
            if (EPI == 1) {
                ((uint32_t*)outgb)[((size_t)r * 128 + c) >> 1] =
                    pack_bf2(acc[mi][ni][0] * s0, acc[mi][ni][1] * s0);
                ((uint32_t*)outgb)[((size_t)(r + 8) * 128 + c) >> 1] =
                    pack_bf2(acc[mi][ni][2] * s1, acc[mi][ni][3] * s1);
            } else {
                float b0 = bias_or_dis[c], b1 = bias_or_dis[c + 1];
                uint32_t hi, lo;
                split2(acc[mi][ni][0] + b0, acc[mi][ni][1] + b1, hi, lo);
                ((uint32_t*)outh)[((size_t)r * 128 + c) >> 1] = hi;
                ((uint32_t*)outl)[((size_t)r * 128 + c) >> 1] = lo;
                split2(acc[mi][ni][2] + b0, acc[mi][ni][3] + b1, hi, lo);
                ((uint32_t*)outh)[((size_t)(r + 8) * 128 + c) >> 1] = hi;
                ((uint32_t*)outl)[((size_t)(r + 8) * 128 + c) >> 1] = lo;
            }
        }
    }
}

// ===========================================================================
// CSR gather (bf16 g) + fused finalize: one warp per node, f32 accumulate.
// h[n] = relu(dis[n] * (sum g[col[e]] + g[n]) + b)  -> bf16 hi/lo planes
// Lane covers cols lane*4 .. lane*4+3 (uint2 = 4 bf16).
// ===========================================================================
__global__ void gather_kernel(const float* __restrict__ b,
                              __nv_bfloat16* __restrict__ outh,
                              __nv_bfloat16* __restrict__ outl) {
    int w = (blockIdx.x * blockDim.x + threadIdx.x) >> 5;
    if (w >= NN) return;
    int lane = threadIdx.x & 31;
    int beg = g_rowptr[w];
    int end = g_rowptr[w + 1];

    const uint2* G = (const uint2*)g_gb;
    float4 a0, a1 = make_float4(0.f, 0.f, 0.f, 0.f);
    {
        uint2 sv = G[(size_t)w * 32 + lane];   // self term
        float2 f0 = unpack_bf2(sv.x), f1 = unpack_bf2(sv.y);
        a0 = make_float4(f0.x, f0.y, f1.x, f1.y);
    }

    int e = beg;
    while (e < end) {
        int cnt = min(end - e, 32);
        int c = (lane < cnt) ? g_col[e + lane] : 0;
        int i = 0;
        for (; i + 8 <= cnt; i += 8) {
            int s0 = __shfl_sync(0xffffffffu, c, i);
            int s1 = __shfl_sync(0xffffffffu, c, i + 1);
            int s2 = __shfl_sync(0xffffffffu, c, i + 2);
            int s3 = __shfl_sync(0xffffffffu, c, i + 3);
            int s4 = __shfl_sync(0xffffffffu, c, i + 4);
            int s5 = __shfl_sync(0xffffffffu, c, i + 5);
            int s6 = __shfl_sync(0xffffffffu, c, i + 6);
            int s7 = __shfl_sync(0xffffffffu, c, i + 7);
            uint2 v0 = G[(size_t)s0 * 32 + lane];
            uint2 v1 = G[(size_t)s1 * 32 + lane];
            uint2 v2 = G[(size_t)s2 * 32 + lane];
            uint2 v3 = G[(size_t)s3 * 32 + lane];
            uint2 v4 = G[(size_t)s4 * 32 + lane];
            uint2 v5 = G[(size_t)s5 * 32 + lane];
            uint2 v6 = G[(size_t)s6 * 32 + lane];
            uint2 v7 = G[(size_t)s7 * 32 + lane];
            float2 f;
            f = unpack_bf2(v0.x); a0.x += f.x; a0.y += f.y;
            f = unpack_bf2(v0.y); a0.z += f.x; a0.w += f.y;
            f = unpack_bf2(v1.x); a1.x += f.x; a1.y += f.y;
            f = unpack_bf2(v1.y); a1.z += f.x; a1.w += f.y;
            f = unpack_bf2(v2.x); a0.x += f.x; a0.y += f.y;
            f = unpack_bf2(v2.y); a0.z += f.x; a0.w += f.y;
            f = unpack_bf2(v3.x); a1.x += f.x; a1.y += f.y;
            f = unpack_bf2(v3.y); a1.z += f.x; a1.w += f.y;
            f = unpack_bf2(v4.x); a0.x += f.x; a0.y += f.y;
            f = unpack_bf2(v4.y); a0.z += f.x; a0.w += f.y;
            f = unpack_bf2(v5.x); a1.x += f.x; a1.y += f.y;
            f = unpack_bf2(v5.y); a1.z += f.x; a1.w += f.y;
            f = unpack_bf2(v6.x); a0.x += f.x; a0.y += f.y;
            f = unpack_bf2(v6.y); a0.z += f.x; a0.w += f.y;
            f = unpack_bf2(v7.x); a1.x += f.x; a1.y += f.y;
            f = unpack_bf2(v7.y); a1.z += f.x; a1.w += f.y;
        }
        for (; i + 4 <= cnt; i += 4) {
            int s0 = __shfl_sync(0xffffffffu, c, i);
            int s1 = __shfl_sync(0xffffffffu, c, i + 1);
            int s2 = __shfl_sync(0xffffffffu, c, i + 2);
            int s3 = __shfl_sync(0xffffffffu, c, i + 3);
            uint2 v0 = G[(size_t)s0 * 32 + lane];
            uint2 v1 = G[(size_t)s1 * 32 + lane];
            uint2 v2 = G[(size_t)s2 * 32 + lane];
            uint2 v3 = G[(size_t)s3 * 32 + lane];
            float2 f;
            f = unpack_bf2(v0.x); a0.x += f.x; a0.y += f.y;
            f = unpack_bf2(v0.y); a0.z += f.x; a0.w += f.y;
            f = unpack_bf2(v1.x); a1.x += f.x; a1.y += f.y;
            f = unpack_bf2(v1.y); a1.z += f.x; a1.w += f.y;
            f = unpack_bf2(v2.x); a0.x += f.x; a0.y += f.y;
            f = unpack_bf2(v2.y); a0.z += f.x; a0.w += f.y;
            f = unpack_bf2(v3.x); a1.x += f.x; a1.y += f.y;
            f = unpack_bf2(v3.y); a1.z += f.x; a1.w += f.y;
        }
        for (; i < cnt; i++) {
            int s0 = __shfl_sync(0xffffffffu, c, i);
            uint2 v0 = G[(size_t)s0 * 32 + lane];
            float2 f;
            f = unpack_bf2(v0.x); a0.x += f.x; a0.y += f.y;
            f = unpack_bf2(v0.y); a0.z += f.x; a0.w += f.y;
        }
        e += cnt;
    }
    a0.x += a1.x; a0.y += a1.y; a0.z += a1.z; a0.w += a1.w;

    float sc = g_dis[w];
    float4 bb = *(const float4*)(b + lane * 4);
    float4 o;
    o.x = fmaxf(fmaf(sc, a0.x, bb.x), 0.0f);
    o.y = fmaxf(fmaf(sc, a0.y, bb.y), 0.0f);
    o.z = fmaxf(fmaf(sc, a0.z, bb.z), 0.0f);
    o.w = fmaxf(fmaf(sc, a0.w, bb.w), 0.0f);

    uint32_t h0, l0, h1, l1;
    split2(o.x, o.y, h0, l0);
    split2(o.z, o.w, h1, l1);
    ((uint2*)outh)[(size_t)w * 32 + lane] = make_uint2(h0, h1);
    ((uint2*)outl)[(size_t)w * 32 + lane] = make_uint2(l0, l1);
}

// ===========================================================================
// Pool (reads bf16 planes) + head
// ===========================================================================
__global__ void pool_kernel(const int* __restrict__ batch,
                            const __nv_bfloat16* __restrict__ ph,
                            const __nv_bfloat16* __restrict__ pl) {
    __shared__ float s[GG * HH];
    __shared__ float c[GG];
    int tid = threadIdx.x;  // 128
#pragma unroll
    for (int i = 0; i < GG; i++) s[i * HH + tid] = 0.0f;
    if (tid < GG) c[tid] = 0.0f;
    __syncthreads();

    for (int n = blockIdx.x; n < NN; n += gridDim.x) {
        int b = batch[n];
        float v = __bfloat162float(ph[(size_t)n * HH + tid]) +
                  __bfloat162float(pl[(size_t)n * HH + tid]);
        s[b * HH + tid] += v;
        if (tid == 0) c[b] += 1.0f;
    }
    __syncthreads();
#pragma unroll
    for (int i = 0; i < GG; i++) atomicAdd(&g_pool[i * HH + tid], s[i * HH + tid]);
    if (tid < GG) atomicAdd(&g_pool[GG * HH + tid], c[tid]);
}

__global__ void head_kernel(const float* __restrict__ Wf1,
                            const float* __restrict__ bf1,
                            const float* __restrict__ Wf2,
                            const float* __restrict__ bf2,
                            float* __restrict__ out) {
    __shared__ float P[GG * HH];
    __shared__ float Z[GG * 64];
    int tid = threadIdx.x;

    for (int i = tid; i < GG * HH; i += 1024) {
        float cnt = g_pool[GG * HH + i / HH];
        P[i] = g_pool[i] / fmaxf(cnt, 1.0f);
    }
    __syncthreads();

    {
        int g = tid >> 6;
        int j = tid & 63;
        float acc = bf1[j];
        const float* p = P + g * HH;
#pragma unroll 8
        for (int k = 0; k < HH; k++) acc += p[k] * Wf1[k * 64 + j];
        Z[g * 64 + j] = fmaxf(acc, 0.0f);
    }
    __syncthreads();

    if (tid < GG * CC) {
        int g = tid / CC;
        int c = tid % CC;
        float acc = bf2[c];
        const float* z = Z + g * 64;
#pragma unroll
        for (int j = 0; j < 64; j++) acc += z[j] * Wf2[j * CC + c];
        out[g * CC + c] = acc;
    }
}

// ===========================================================================
extern "C" void kernel_launch(void* const* d_in, const int* in_sizes, int n_in,
                              void* d_out, int out_size) {
    const float* x = (const float*)d_in[0];
    const int* edge = (const int*)d_in[1];     // int32
    const int* batch = (const int*)d_in[2];    // int32
    const float* W_in = (const float*)d_in[3];
    const float* b_in = (const float*)d_in[4];
    const float* W1 = (const float*)d_in[5];
    const float* b1 = (const float*)d_in[6];
    const float* W2 = (const float*)d_in[7];
    const float* b2 = (const float*)d_in[8];
    const float* Wf1 = (const float*)d_in[9];
    const float* bf1 = (const float*)d_in[10];
    const float* Wf2 = (const float*)d_in[11];
    const float* bf2 = (const float*)d_in[12];
    float* out = (float*)d_out;

    const int* src = edge;
    const int* dst = edge + EE;

    void *p_deg, *p_pool, *p_gb, *p_dis;
    void *p_pah, *p_pal, *p_pbh, *p_pbl, *p_wh, *p_wl;
    cudaGetSymbolAddress(&p_deg, g_deg);
    cudaGetSymbolAddress(&p_pool, g_pool);
    cudaGetSymbolAddress(&p_gb, g_gb);
    cudaGetSymbolAddress(&p_dis, g_dis);
    cudaGetSymbolAddress(&p_pah, g_pah);
    cudaGetSymbolAddress(&p_pal, g_pal);
    cudaGetSymbolAddress(&p_pbh, g_pbh);
    cudaGetSymbolAddress(&p_pbl, g_pbl);
    cudaGetSymbolAddress(&p_wh, g_wh);
    cudaGetSymbolAddress(&p_wl, g_wl);
    __nv_bfloat16* pah = (__nv_bfloat16*)p_pah;
    __nv_bfloat16* pal = (__nv_bfloat16*)p_pal;
    __nv_bfloat16* pbh = (__nv_bfloat16*)p_pbh;
    __nv_bfloat16* pbl = (__nv_bfloat16*)p_pbl;
    __nv_bfloat16* wh = (__nv_bfloat16*)p_wh;
    __nv_bfloat16* wl = (__nv_bfloat16*)p_wl;
    __nv_bfloat16* gb = (__nv_bfloat16*)p_gb;

    cudaFuncSetAttribute(gemm2<0>, cudaFuncAttributeMaxDynamicSharedMemorySize, SM_GEMM_TOTAL);
    cudaFuncSetAttribute(gemm2<1>, cudaFuncAttributeMaxDynamicSharedMemorySize, SM_GEMM_TOTAL);

    // CSR build + dis (coalesced scan)
    cudaMemsetAsync(p_deg, 0, NN * sizeof(int));
    deg_kernel<<<(EE / 4 + 255) / 256, 256>>>(dst);
    scan1_kernel<<<40, 1024>>>();
    scan2_kernel<<<1, 64>>>();
    scan3_kernel<<<40, 1024>>>();
    fill_kernel<<<(EE / 4 + 255) / 256, 256>>>(src, dst);

    // Conversions
    conv_w_kernel<<<dim3(64, 3), 256>>>(W_in, W1, W2);
    conv_x_kernel<<<(NP * 32 + 255) / 256, 256>>>(x);

    const int gemmGrid = NP / 128;  // 313

    // h0 = x @ W_in + b_in  (planes A -> planes B)
    gemm2<0><<<gemmGrid, 256, SM_GEMM_TOTAL>>>(pah, pal, wh, wl, b_in,
                                               nullptr, pbh, pbl);
    // Layer 1: g = (h0 @ W1) * dis (bf16); h1 = relu(dis*(gather+self)+b1) -> planes A
    gemm2<1><<<gemmGrid, 256, SM_GEMM_TOTAL>>>(pbh, pbl, wh + HH * HH, wl + HH * HH,
                                               (const float*)p_dis, gb, nullptr, nullptr);
    gather_kernel<<<(NN * 32 + 255) / 256, 256>>>(b1, pah, pal);

    // Layer 2: planes A -> g -> planes B
    gemm2<1><<<gemmGrid, 256, SM_GEMM_TOTAL>>>(pah, pal, wh + 2 * HH * HH, wl + 2 * HH * HH,
                                               (const float*)p_dis, gb, nullptr, nullptr);
    gather_kernel<<<(NN * 32 + 255) / 256, 256>>>(b2, pbh, pbl);

    // Pool + head
    cudaMemsetAsync(p_pool, 0, (GG * HH + GG) * sizeof(float));
    pool_kernel<<<256, 128>>>(batch, pbh, pbl);
    head_kernel<<<1, 1024>>>(Wf1, bf1, Wf2, bf2, out);
}